// round 5
// baseline (speedup 1.0000x reference)
#include <cuda_runtime.h>

// B=8, T=2048, V=1024.
// c = idx[b,t]; q_1..q_m = occurrences of c in [0..t]; Cv(r) = inclusive prefix
// histogram. Then
//   L_t[v] = w2*( m*Cv(t) - sum_j Cv(q_j-1) ) + a0*m*[v==c]
//            + a1*#{j : q_j+1 <= t, idx(q_j+1)==v},   out = softmax(L_t).
// Cv checkpointed every 32 positions (u16, L2-resident); occurrences in a CSR
// list per (b, token). Setup fully fused into one kernel (1 block per b).
// Main: one warp per t, packed 2xu16 SIMD gather, warp-private smem bins.

namespace {
constexpr int B = 8, T = 2048, V = 1024;
constexpr int SEG = 32, NSEG = T / SEG;
}

__device__ __align__(16) unsigned short g_cp[B][NSEG][V];  // excl. prefix ckpt
__device__ __align__(16) unsigned short g_row[B][T];
__device__ __align__(16) unsigned short g_off[B][V];       // CSR offsets
__device__ __align__(16) unsigned short g_occ[B][T];       // CSR positions

// ---- fused setup: zero + seg hist + prefix + offsets + CSR fill ----
__global__ __launch_bounds__(1024) void k_setup(const int* __restrict__ idx) {
    __shared__ unsigned short srow[T];
    __shared__ unsigned wsum[32];
    const int b = blockIdx.x;
    const int tid = threadIdx.x, lane = tid & 31, warp = tid >> 5;

    // row load (2 tokens/thread) + zero this b's checkpoint slab (128 KB)
    const int2 tt = reinterpret_cast<const int2*>(idx + b * T)[tid];
    srow[2 * tid]     = (unsigned short)tt.x;
    srow[2 * tid + 1] = (unsigned short)tt.y;
    reinterpret_cast<ushort2*>(g_row[b])[tid] =
        make_ushort2((unsigned short)tt.x, (unsigned short)tt.y);
    const uint4 z = make_uint4(0, 0, 0, 0);
    #pragma unroll
    for (int k = 0; k < 8; k++)
        reinterpret_cast<uint4*>(&g_cp[b][0][0])[k * 1024 + tid] = z;
    __syncthreads();

    // per-segment counts via match_any (warp w handles segments w, w+32)
    #pragma unroll
    for (int sg = warp; sg < NSEG; sg += 32) {
        const unsigned tok = srow[sg * 32 + lane];
        const unsigned mask = __match_any_sync(0xffffffffu, tok);
        if ((mask & ((1u << lane) - 1u)) == 0u)
            g_cp[b][sg][tok] = (unsigned short)__popc(mask);
    }
    __syncthreads();

    // in-place exclusive prefix over segments; thread owns v = tid
    unsigned run = 0;
    #pragma unroll 8
    for (int k = 0; k < NSEG; k++) {
        const unsigned x = g_cp[b][k][tid];
        g_cp[b][k][tid] = (unsigned short)run;
        run += x;
    }

    // block exclusive scan of per-v totals -> CSR offsets
    const unsigned total = run;
    unsigned incl = total;
    #pragma unroll
    for (int o = 1; o < 32; o <<= 1) {
        const unsigned n = __shfl_up_sync(0xffffffffu, incl, o);
        if (lane >= o) incl += n;
    }
    if (lane == 31) wsum[warp] = incl;
    __syncthreads();
    unsigned wex = 0;
    #pragma unroll
    for (int w = 0; w < 32; w++)
        if (w < warp) wex += wsum[w];
    g_off[b][tid] = (unsigned short)(wex + incl - total);
    __syncthreads();

    // CSR fill (sorted by construction)
    #pragma unroll
    for (int sg = warp; sg < NSEG; sg += 32) {
        const int s = sg * 32 + lane;
        const unsigned tok = srow[s];
        const unsigned mask = __match_any_sync(0xffffffffu, tok);
        const int rank = __popc(mask & ((1u << lane) - 1u));
        const int slot = (int)g_off[b][tok] + (int)g_cp[b][sg][tok] + rank;
        g_occ[b][slot] = (unsigned short)s;
    }
}

// ---- main: one warp per t; 4 warps x 4 t's per block; no block barriers
//      after the initial cooperative smem fill ----
__global__ __launch_bounds__(128) void k4_main(const float* __restrict__ vw,
                                               float* __restrict__ out) {
    __shared__ float acc[4][V];              // 16 KB warp-private bins
    __shared__ unsigned short srow[T];       // 4 KB token row
    __shared__ unsigned short scp[V];        // 2 KB this block's ckpt row
    const int b = blockIdx.y;
    const int t_base = blockIdx.x * 16;      // 16 t's, all in one segment pair? no: one segment
    const int p = t_base >> 5;
    const int seg0 = p << 5;
    const int tid = threadIdx.x, lane = tid & 31, warp = tid >> 5;
    float* const wacc = acc[warp];
    const int voff = lane * 4;               // lane owns v = k*128 + voff + 0..3

    // cooperative smem fill
    reinterpret_cast<uint4*>(srow)[tid] =
        reinterpret_cast<const uint4*>(g_row[b])[tid];
    reinterpret_cast<uint4*>(srow)[tid + 128] =
        reinterpret_cast<const uint4*>(g_row[b])[tid + 128];
    reinterpret_cast<uint4*>(scp)[tid] =
        reinterpret_cast<const uint4*>(&g_cp[b][p][0])[tid];
    #pragma unroll
    for (int k = 0; k < 8; k++)
        *reinterpret_cast<float4*>(&wacc[k * 128 + voff]) =
            make_float4(0.f, 0.f, 0.f, 0.f);
    __syncthreads();

    const unsigned stok = srow[seg0 + lane];
    const float w0 = vw[0], w1 = vw[1], w2 = vw[2];
    const float a0 = w0 - w2, a1 = w1 - w2;
    const unsigned short* const cpz = &g_cp[b][0][0];   // row 0 == all zeros

    for (int i = 0; i < 4; i++) {
        const int t = t_base + warp * 4 + i;
        const int ti = t - seg0;             // 0..31
        const unsigned c = __shfl_sync(0xffffffffu, stok, ti);
        const unsigned ball = __ballot_sync(0xffffffffu, stok == c);
        const int m = (int)scp[c] + __popc(ball & ((2u << ti) - 1u));
        const int offc = g_off[b][c];
        const float fm = (float)m;
        const bool fast = (m <= 31);         // m*CP <= 31*2048 < 2^16
        const unsigned mu = fast ? (unsigned)m : 0u;

        // packed 2xu16 SIMD: pa = m*CP[p] - sum_j CP[(q_j-1)>>5]
        unsigned pa[16];
        #pragma unroll
        for (int k = 0; k < 8; k++) {
            const uint2 w = *reinterpret_cast<const uint2*>(&scp[k * 128 + voff]);
            pa[2 * k]     = mu * w.x;
            pa[2 * k + 1] = mu * w.y;
        }

        for (int jb = 0; jb < m; jb += 32) {
            const int nj = min(32, m - jb);
            const unsigned qv =
                (lane < nj) ? (unsigned)g_occ[b][offc + jb + lane] : 0u;

            // gather pass: pair-unrolled, branch-free (q==0 / pad -> zero row)
            if (fast) {
                for (int j = 0; j < nj; j += 2) {
                    const int q0 = __shfl_sync(0xffffffffu, qv, j);
                    const int q1 = (j + 1 < nj)
                                 ? __shfl_sync(0xffffffffu, qv, j + 1) : 0;
                    const unsigned short* r0 =
                        cpz + (q0 > 0 ? ((q0 - 1) >> 5) * V : 0);
                    const unsigned short* r1 =
                        cpz + (q1 > 0 ? ((q1 - 1) >> 5) * V : 0);
                    #pragma unroll
                    for (int k = 0; k < 8; k++) {
                        const uint2 u0 =
                            *reinterpret_cast<const uint2*>(r0 + k * 128 + voff);
                        const uint2 u1 =
                            *reinterpret_cast<const uint2*>(r1 + k * 128 + voff);
                        pa[2 * k]     -= u0.x + u1.x;   // lo/hi sums < 2^16
                        pa[2 * k + 1] -= u0.y + u1.y;
                    }
                }
            }

            // atomics pass: sub-checkpoint remainder of Cv(q-1) + bigram
            for (int j = 0; j < nj; j++) {
                const int q = __shfl_sync(0xffffffffu, qv, j);
                if (q > 0) {
                    const int qm1 = q - 1, qp = qm1 >> 5;
                    const unsigned rtok = srow[(qp << 5) + lane];
                    if (lane <= (qm1 & 31)) atomicAdd(&wacc[rtok], -w2);
                }
                if (q < t && lane == 0)
                    atomicAdd(&wacc[srow[q + 1]], a1);
            }
        }

        if (!fast) {  // exact cold path for m > 31 (i32, overflow-safe)
            #pragma unroll 1
            for (int k = 0; k < 8; k++) {
                const uint2 w =
                    *reinterpret_cast<const uint2*>(&scp[k * 128 + voff]);
                int l0 = m * (int)(w.x & 0xffffu);
                int l1 = m * (int)(w.x >> 16);
                int l2 = m * (int)(w.y & 0xffffu);
                int l3 = m * (int)(w.y >> 16);
                for (int j = 0; j < m; j++) {
                    const int q = g_occ[b][offc + j];
                    if (q > 0) {
                        const uint2 u = *reinterpret_cast<const uint2*>(
                            cpz + ((q - 1) >> 5) * V + k * 128 + voff);
                        l0 -= (int)(u.x & 0xffffu); l1 -= (int)(u.x >> 16);
                        l2 -= (int)(u.y & 0xffffu); l3 -= (int)(u.y >> 16);
                    }
                }
                atomicAdd(&wacc[k * 128 + voff + 0], w2 * (float)l0);
                atomicAdd(&wacc[k * 128 + voff + 1], w2 * (float)l1);
                atomicAdd(&wacc[k * 128 + voff + 2], w2 * (float)l2);
                atomicAdd(&wacc[k * 128 + voff + 3], w2 * (float)l3);
            }
        }

        // remainder of Cv(t) over this segment + a0 term
        if (lane <= ti) atomicAdd(&wacc[stok], w2 * fm);
        if (lane == ti) atomicAdd(&wacc[c], a0 * fm);
        __syncwarp();

        // assemble logits (unpack packed counts), warp-local softmax
        float a[32];
        float vmax = -3.0e38f;
        #pragma unroll
        for (int k = 0; k < 8; k++) {
            const float4 av =
                *reinterpret_cast<const float4*>(&wacc[k * 128 + voff]);
            *reinterpret_cast<float4*>(&wacc[k * 128 + voff]) =
                make_float4(0.f, 0.f, 0.f, 0.f);     // re-zero for next t
            a[4 * k + 0] = fast ? fmaf(w2, (float)(pa[2 * k] & 0xffffu), av.x) : av.x;
            a[4 * k + 1] = fast ? fmaf(w2, (float)(pa[2 * k] >> 16), av.y) : av.y;
            a[4 * k + 2] = fast ? fmaf(w2, (float)(pa[2 * k + 1] & 0xffffu), av.z) : av.z;
            a[4 * k + 3] = fast ? fmaf(w2, (float)(pa[2 * k + 1] >> 16), av.w) : av.w;
            vmax = fmaxf(vmax, fmaxf(fmaxf(a[4 * k], a[4 * k + 1]),
                                     fmaxf(a[4 * k + 2], a[4 * k + 3])));
        }
        #pragma unroll
        for (int o = 16; o; o >>= 1)
            vmax = fmaxf(vmax, __shfl_xor_sync(0xffffffffu, vmax, o));

        float ssum = 0.f;
        #pragma unroll
        for (int k = 0; k < 32; k++) {
            a[k] = __expf(a[k] - vmax);
            ssum += a[k];
        }
        #pragma unroll
        for (int o = 16; o; o >>= 1)
            ssum += __shfl_xor_sync(0xffffffffu, ssum, o);
        const float inv = 1.0f / ssum;

        float* const orow = out + (size_t)(b * T + t) * V + voff;
        #pragma unroll
        for (int k = 0; k < 8; k++)
            *reinterpret_cast<float4*>(orow + k * 128) =
                make_float4(a[4 * k] * inv, a[4 * k + 1] * inv,
                            a[4 * k + 2] * inv, a[4 * k + 3] * inv);

        __syncwarp();   // acc re-zero visible before next t's atomics
    }
}

extern "C" void kernel_launch(void* const* d_in, const int* in_sizes, int n_in,
                              void* d_out, int out_size) {
    const int*   idx = (const int*)d_in[0];
    const float* vw  = (const float*)d_in[1];
    float*       out = (float*)d_out;
    (void)in_sizes; (void)n_in; (void)out_size;

    k_setup<<<dim3(B), 1024>>>(idx);
    k4_main<<<dim3(T / 16, B), 128>>>(vw, out);
}

// round 6
// speedup vs baseline: 1.0715x; 1.0715x over previous
#include <cuda_runtime.h>

// B=8, T=2048, V=1024.
// c = idx[b,t]; q_1..q_m = occurrences of c in [0..t]; Cv(r) = inclusive prefix
// histogram. Then
//   L_t[v] = w2*( m*Cv(t) - sum_j Cv(q_j-1) ) + a0*m*[v==c]
//            + a1*#{j : q_j+1 <= t, idx(q_j+1)==v},   out = softmax(L_t).
// Cv checkpointed every 32 positions (u16, L2-resident); occurrences in a CSR
// list per (b, token). Setup fused into one kernel (1 block per b).
// Main: one warp per t (2 t's/warp), packed 2xu16 SIMD gather, warp-private
// smem bins, no block barriers.

namespace {
constexpr int B = 8, T = 2048, V = 1024;
constexpr int NSEG = T / 32;
constexpr int TPW = 2;                      // t's per warp
constexpr int TPB = 4 * TPW;                // t's per block (4 warps)
}

__device__ __align__(16) unsigned short g_cp[B][NSEG][V];  // excl. prefix ckpt
__device__ __align__(16) unsigned short g_row[B][T];
__device__ __align__(16) unsigned short g_off[B][V];       // CSR offsets
__device__ __align__(16) unsigned short g_occ[B][T];       // CSR positions

// ---- fused setup: zero + seg hist + prefix + offsets + CSR fill ----
__global__ __launch_bounds__(1024) void k_setup(const int* __restrict__ idx) {
    __shared__ unsigned short srow[T];
    __shared__ unsigned wsum[32];
    const int b = blockIdx.x;
    const int tid = threadIdx.x, lane = tid & 31, warp = tid >> 5;

    const int2 tt = reinterpret_cast<const int2*>(idx + b * T)[tid];
    srow[2 * tid]     = (unsigned short)tt.x;
    srow[2 * tid + 1] = (unsigned short)tt.y;
    reinterpret_cast<ushort2*>(g_row[b])[tid] =
        make_ushort2((unsigned short)tt.x, (unsigned short)tt.y);
    const uint4 z = make_uint4(0, 0, 0, 0);
    #pragma unroll
    for (int k = 0; k < 8; k++)
        reinterpret_cast<uint4*>(&g_cp[b][0][0])[k * 1024 + tid] = z;
    __syncthreads();

    #pragma unroll
    for (int sg = warp; sg < NSEG; sg += 32) {
        const unsigned tok = srow[sg * 32 + lane];
        const unsigned mask = __match_any_sync(0xffffffffu, tok);
        if ((mask & ((1u << lane) - 1u)) == 0u)
            g_cp[b][sg][tok] = (unsigned short)__popc(mask);
    }
    __syncthreads();

    unsigned run = 0;
    #pragma unroll 8
    for (int k = 0; k < NSEG; k++) {
        const unsigned x = g_cp[b][k][tid];
        g_cp[b][k][tid] = (unsigned short)run;
        run += x;
    }

    const unsigned total = run;
    unsigned incl = total;
    #pragma unroll
    for (int o = 1; o < 32; o <<= 1) {
        const unsigned n = __shfl_up_sync(0xffffffffu, incl, o);
        if (lane >= o) incl += n;
    }
    if (lane == 31) wsum[warp] = incl;
    __syncthreads();
    unsigned wex = 0;
    #pragma unroll
    for (int w = 0; w < 32; w++)
        if (w < warp) wex += wsum[w];
    g_off[b][tid] = (unsigned short)(wex + incl - total);
    __syncthreads();

    #pragma unroll
    for (int sg = warp; sg < NSEG; sg += 32) {
        const int s = sg * 32 + lane;
        const unsigned tok = srow[s];
        const unsigned mask = __match_any_sync(0xffffffffu, tok);
        const int rank = __popc(mask & ((1u << lane) - 1u));
        const int slot = (int)g_off[b][tok] + (int)g_cp[b][sg][tok] + rank;
        g_occ[b][slot] = (unsigned short)s;
    }
}

// ---- main: one warp per t; 4 warps x TPW t's per block; no block barriers ----
__global__ __launch_bounds__(128, 8) void k4_main(const float* __restrict__ vw,
                                                  float* __restrict__ out) {
    __shared__ float acc[4][V];             // warp-private bins
    const int b = blockIdx.y;
    const int t_base = blockIdx.x * TPB;    // TPB t's, all in one segment
    const int p = t_base >> 5;
    const int seg0 = p << 5;
    const int tid = threadIdx.x, lane = tid & 31, warp = tid >> 5;
    float* const wacc = acc[warp];
    const int voff = lane * 4;              // lane owns v = k*128 + voff + 0..3

    #pragma unroll
    for (int k = 0; k < 8; k++)
        *reinterpret_cast<float4*>(&wacc[k * 128 + voff]) =
            make_float4(0.f, 0.f, 0.f, 0.f);

    const unsigned stok = g_row[b][seg0 + lane];
    const float w0 = vw[0], w1 = vw[1], w2 = vw[2];
    const float a0 = w0 - w2, a1 = w1 - w2;
    const unsigned short* const cprow_p = &g_cp[b][p][0];
    __syncwarp();

    for (int i = 0; i < TPW; i++) {
        const int t = t_base + warp * TPW + i;
        const int ti = t - seg0;            // 0..31
        const unsigned c = __shfl_sync(0xffffffffu, stok, ti);
        const unsigned ball = __ballot_sync(0xffffffffu, stok == c);
        const int m = (int)g_cp[b][p][c] + __popc(ball & ((2u << ti) - 1u));
        const int offc = g_off[b][c];
        const float fm = (float)m;
        const bool fast = (m <= 31);        // m*CP <= 31*2048 < 2^16
        const unsigned mu = fast ? (unsigned)m : 0u;

        // packed 2xu16 SIMD: pa = m*CP[p] - sum_j CP[(q_j-1)>>5]
        unsigned pa[16];
        #pragma unroll
        for (int k = 0; k < 8; k++) {
            const uint2 w =
                *reinterpret_cast<const uint2*>(cprow_p + k * 128 + voff);
            pa[2 * k]     = mu * w.x;
            pa[2 * k + 1] = mu * w.y;
        }

        for (int jb = 0; jb < m; jb += 32) {
            const int nj = min(32, m - jb);
            unsigned qv = 0;
            if (lane < nj) qv = g_occ[b][offc + jb + lane];
            for (int j = 0; j < nj; j++) {
                const int q = __shfl_sync(0xffffffffu, qv, j);
                if (q > 0) {
                    const int qm1 = q - 1, qp = qm1 >> 5;
                    if (fast) {
                        const unsigned short* rowq = &g_cp[b][qp][0];
                        #pragma unroll
                        for (int k = 0; k < 8; k++) {
                            const uint2 w = *reinterpret_cast<const uint2*>(
                                rowq + k * 128 + voff);
                            pa[2 * k]     -= w.x;
                            pa[2 * k + 1] -= w.y;
                        }
                    }
                    // sub-checkpoint remainder of Cv(q-1)
                    const unsigned rtok = g_row[b][(qp << 5) + lane];
                    if (lane <= (qm1 & 31))
                        atomicAdd(&wacc[rtok], -w2);
                }
                if (q < t && lane == 0)     // bigram c -> next token
                    atomicAdd(&wacc[g_row[b][q + 1]], a1);
            }
        }

        if (!fast) {  // exact cold path for m > 31 (i32, overflow-safe)
            #pragma unroll 1
            for (int k = 0; k < 8; k++) {
                const uint2 w =
                    *reinterpret_cast<const uint2*>(cprow_p + k * 128 + voff);
                int l0 = m * (int)(w.x & 0xffffu);
                int l1 = m * (int)(w.x >> 16);
                int l2 = m * (int)(w.y & 0xffffu);
                int l3 = m * (int)(w.y >> 16);
                for (int j = 0; j < m; j++) {
                    const int q = g_occ[b][offc + j];
                    if (q > 0) {
                        const uint2 u = *reinterpret_cast<const uint2*>(
                            &g_cp[b][(q - 1) >> 5][0] + k * 128 + voff);
                        l0 -= (int)(u.x & 0xffffu); l1 -= (int)(u.x >> 16);
                        l2 -= (int)(u.y & 0xffffu); l3 -= (int)(u.y >> 16);
                    }
                }
                atomicAdd(&wacc[k * 128 + voff + 0], w2 * (float)l0);
                atomicAdd(&wacc[k * 128 + voff + 1], w2 * (float)l1);
                atomicAdd(&wacc[k * 128 + voff + 2], w2 * (float)l2);
                atomicAdd(&wacc[k * 128 + voff + 3], w2 * (float)l3);
            }
        }

        // remainder of Cv(t) over this segment + a0 term
        if (lane <= ti) atomicAdd(&wacc[stok], w2 * fm);
        if (lane == ti) atomicAdd(&wacc[c], a0 * fm);
        __syncwarp();

        // assemble logits (unpack packed counts), warp-local softmax
        float a[32];
        float vmax = -3.0e38f;
        #pragma unroll
        for (int k = 0; k < 8; k++) {
            const float4 av =
                *reinterpret_cast<const float4*>(&wacc[k * 128 + voff]);
            *reinterpret_cast<float4*>(&wacc[k * 128 + voff]) =
                make_float4(0.f, 0.f, 0.f, 0.f);  // re-zero for next t
            a[4 * k + 0] = fmaf(w2, (float)(pa[2 * k] & 0xffffu),     av.x);
            a[4 * k + 1] = fmaf(w2, (float)(pa[2 * k] >> 16),         av.y);
            a[4 * k + 2] = fmaf(w2, (float)(pa[2 * k + 1] & 0xffffu), av.z);
            a[4 * k + 3] = fmaf(w2, (float)(pa[2 * k + 1] >> 16),     av.w);
            vmax = fmaxf(vmax, fmaxf(fmaxf(a[4 * k], a[4 * k + 1]),
                                     fmaxf(a[4 * k + 2], a[4 * k + 3])));
        }
        #pragma unroll
        for (int o = 16; o; o >>= 1)
            vmax = fmaxf(vmax, __shfl_xor_sync(0xffffffffu, vmax, o));

        float ssum = 0.f;
        #pragma unroll
        for (int k = 0; k < 32; k++) {
            a[k] = __expf(a[k] - vmax);
            ssum += a[k];
        }
        #pragma unroll
        for (int o = 16; o; o >>= 1)
            ssum += __shfl_xor_sync(0xffffffffu, ssum, o);
        const float inv = 1.0f / ssum;

        float* const orow = out + (size_t)(b * T + t) * V + voff;
        #pragma unroll
        for (int k = 0; k < 8; k++)
            *reinterpret_cast<float4*>(orow + k * 128) =
                make_float4(a[4 * k] * inv, a[4 * k + 1] * inv,
                            a[4 * k + 2] * inv, a[4 * k + 3] * inv);

        __syncwarp();   // acc re-zero visible before next t's atomics
    }
}

extern "C" void kernel_launch(void* const* d_in, const int* in_sizes, int n_in,
                              void* d_out, int out_size) {
    const int*   idx = (const int*)d_in[0];
    const float* vw  = (const float*)d_in[1];
    float*       out = (float*)d_out;
    (void)in_sizes; (void)n_in; (void)out_size;

    k_setup<<<dim3(B), 1024>>>(idx);
    k4_main<<<dim3(T / TPB, B), 128>>>(vw, out);
}